// round 8
// baseline (speedup 1.0000x reference)
#include <cuda_runtime.h>
#include <cuda_bf16.h>
#include <cuda_fp16.h>
#include <cstdint>

#define N_MAX 100000
#define E_MAX 1700000
#define D 128
#define SCAN_B 1024
#define MAX_BLOCKS 128   // >= ceil(N_MAX/SCAN_B) = 98, power of two for scanB

// ---------------- scratch (static device globals) ----------------
__device__ __align__(16) float  g_buf[N_MAX * D];   // g[u] = dinv[u] * (x@W)[u], fp32
__device__ __align__(16) __half g_h16[N_MAX * D];   // fp16 copy for neighbor gathers
__device__ __align__(16) float  g_x[N_MAX * D];     // ping buffer for layer outputs
__device__ float g_dinv[N_MAX];
__device__ int   g_cnt[N_MAX];
__device__ int   g_rowptr[N_MAX + 1];
__device__ int   g_cursor[N_MAX];
__device__ int   g_blocksum[MAX_BLOCKS];
__device__ int   g_blockoff[MAX_BLOCKS];
__device__ int   g_csr[E_MAX];
__device__ __align__(16) __nv_bfloat16 g_wt_hi[3 * D * D];  // W^T hi split, [l][n][k]
__device__ __align__(16) __nv_bfloat16 g_wt_lo[3 * D * D];  // W^T lo split

// ---------------- degree histogram / scan / CSR ----------------
__global__ void cnt_zero(int n) {
    int i = blockIdx.x * blockDim.x + threadIdx.x;
    if (i < n) g_cnt[i] = 0;
}
__global__ void cnt_count(const int* __restrict__ dst, int E) {
    int i = blockIdx.x * blockDim.x + threadIdx.x;
    if (i < E) atomicAdd(&g_cnt[__ldg(&dst[i])], 1);
}
__global__ void scanA(int n) {
    __shared__ int s[SCAN_B];
    int i = blockIdx.x * SCAN_B + threadIdx.x;
    s[threadIdx.x] = (i < n) ? g_cnt[i] : 0;
    __syncthreads();
    for (int off = SCAN_B / 2; off > 0; off >>= 1) {
        if (threadIdx.x < off) s[threadIdx.x] += s[threadIdx.x + off];
        __syncthreads();
    }
    if (threadIdx.x == 0) g_blocksum[blockIdx.x] = s[0];
}
__global__ void scanB(int nblocks, int n) {
    __shared__ int s[MAX_BLOCKS];
    int t = threadIdx.x;
    int v = (t < nblocks) ? g_blocksum[t] : 0;
    s[t] = v; __syncthreads();
    for (int off = 1; off < MAX_BLOCKS; off <<= 1) {
        int u = (t >= off) ? s[t - off] : 0;
        __syncthreads();
        s[t] += u;
        __syncthreads();
    }
    if (t < nblocks) g_blockoff[t] = s[t] - v;
    if (t == nblocks - 1) g_rowptr[n] = s[t];
}
__global__ void scanC(int n) {
    __shared__ int s[SCAN_B];
    int i = blockIdx.x * SCAN_B + threadIdx.x;
    int v = (i < n) ? g_cnt[i] : 0;
    s[threadIdx.x] = v;
    __syncthreads();
    for (int off = 1; off < SCAN_B; off <<= 1) {
        int t = (threadIdx.x >= off) ? s[threadIdx.x - off] : 0;
        __syncthreads();
        s[threadIdx.x] += t;
        __syncthreads();
    }
    if (i < n) {
        int excl = s[threadIdx.x] - v + g_blockoff[blockIdx.x];
        g_rowptr[i] = excl;
        g_cursor[i] = excl;
        g_dinv[i]   = rsqrtf((float)(v + 1));
    }
}
__global__ void fill_csr(const int* __restrict__ src, const int* __restrict__ dst, int E) {
    int i = blockIdx.x * blockDim.x + threadIdx.x;
    if (i < E) {
        int d = __ldg(&dst[i]);
        int pos = atomicAdd(&g_cursor[d], 1);
        g_csr[pos] = __ldg(&src[i]);
    }
}

// ---------------- W^T split prep (once per call) ----------------
__global__ void prep_wt(const float* __restrict__ W0, const float* __restrict__ W1,
                        const float* __restrict__ W2) {
    int idx = blockIdx.x * blockDim.x + threadIdx.x;
    if (idx >= 3 * D * D) return;
    int l = idx / (D * D);
    int r = idx % (D * D);
    int n = r >> 7, k = r & 127;
    const float* W = (l == 0) ? W0 : ((l == 1) ? W1 : W2);
    float f = W[k * D + n];
    __nv_bfloat16 h = __float2bfloat16(f);
    float lo = f - __bfloat162float(h);
    g_wt_hi[idx] = h;
    g_wt_lo[idx] = __float2bfloat16(lo);
}

// ---------------- bf16x3 GEMM via mma.sync (HMMA, baseline PTX) ----------------
// g_buf = dinv .* (X @ W), plus fp16 copy. CTA: 128x128 tile, 512 threads = 16 warps,
// warp tile 32x32 = 2 x 4 m16n8k16 tiles. 3-term split Ah*Bh + Ah*Bl + Al*Bh.
#define PITCH 68   // b32 per smem row: bank = (4*g + tig) % 32, conflict-free
#define SM_TILE_B32 (128 * PITCH)
#define SM_TOTAL (4 * SM_TILE_B32 * 4)   // 139264 bytes

__device__ __forceinline__ void mma16816(float* c, const uint32_t* a, const uint32_t* b) {
    asm volatile(
        "mma.sync.aligned.m16n8k16.row.col.f32.bf16.bf16.f32 "
        "{%0,%1,%2,%3}, {%4,%5,%6,%7}, {%8,%9}, {%0,%1,%2,%3};"
        : "+f"(c[0]), "+f"(c[1]), "+f"(c[2]), "+f"(c[3])
        : "r"(a[0]), "r"(a[1]), "r"(a[2]), "r"(a[3]), "r"(b[0]), "r"(b[1]));
}

template <bool FROM_GX>
__global__ __launch_bounds__(512)
void gemm_mma(const float* __restrict__ Xin, int layer, int nrows) {
    extern __shared__ uint32_t smem[];
    uint32_t* A_hi = smem;
    uint32_t* A_lo = A_hi + SM_TILE_B32;
    uint32_t* B_hi = A_lo + SM_TILE_B32;
    uint32_t* B_lo = B_hi + SM_TILE_B32;

    const float* X = FROM_GX ? (const float*)g_x : Xin;
    const int tid = threadIdx.x;
    const int m0  = blockIdx.x * 128;

    // --- load X tile (128x128 f32), split to bf16 hi/lo in smem ---
    #pragma unroll
    for (int i = 0; i < 8; i++) {
        int id  = tid + i * 512;            // 0..4095 float4 slots
        int row = id >> 5;                  // 128 rows
        int kq  = id & 31;                  // float4 index (k = kq*4)
        float4 v = make_float4(0.f, 0.f, 0.f, 0.f);
        int gr = m0 + row;
        if (gr < nrows) v = *(const float4*)&X[(size_t)gr * D + kq * 4];
        __nv_bfloat162 h01, h23, l01, l23;
        h01.x = __float2bfloat16(v.x); h01.y = __float2bfloat16(v.y);
        h23.x = __float2bfloat16(v.z); h23.y = __float2bfloat16(v.w);
        l01.x = __float2bfloat16(v.x - __bfloat162float(h01.x));
        l01.y = __float2bfloat16(v.y - __bfloat162float(h01.y));
        l23.x = __float2bfloat16(v.z - __bfloat162float(h23.x));
        l23.y = __float2bfloat16(v.w - __bfloat162float(h23.y));
        int base = row * PITCH + kq * 2;
        A_hi[base]     = *(uint32_t*)&h01;
        A_hi[base + 1] = *(uint32_t*)&h23;
        A_lo[base]     = *(uint32_t*)&l01;
        A_lo[base + 1] = *(uint32_t*)&l23;
    }

    // --- copy W^T hi/lo ([n][k] bf16, row = 16 uint4) into padded smem ---
    {
        const uint4* wh = (const uint4*)&g_wt_hi[layer * D * D];
        const uint4* wl = (const uint4*)&g_wt_lo[layer * D * D];
        #pragma unroll
        for (int i = 0; i < 4; i++) {
            int id = tid + i * 512;         // 0..2047
            int n  = id >> 4;               // 128 rows
            int q  = id & 15;               // 16 uint4 per row
            *(uint4*)(B_hi + n * PITCH + q * 4) = wh[n * 16 + q];
            *(uint4*)(B_lo + n * PITCH + q * 4) = wl[n * 16 + q];
        }
    }
    __syncthreads();

    // --- warp MMA ---
    const int wid  = tid >> 5;
    const int lane = tid & 31;
    const int g    = lane >> 2;             // 0..7
    const int tig  = lane & 3;              // 0..3
    const int wm   = (wid & 3) * 32;        // warp row offset
    const int wn   = (wid >> 2) * 32;       // warp col offset

    float acc[2][4][4];
    #pragma unroll
    for (int mt = 0; mt < 2; mt++)
        #pragma unroll
        for (int nt = 0; nt < 4; nt++)
            #pragma unroll
            for (int e = 0; e < 4; e++) acc[mt][nt][e] = 0.f;

    #pragma unroll
    for (int split = 0; split < 3; split++) {
        const uint32_t* Ap = (split == 2) ? A_lo : A_hi;
        const uint32_t* Bp = (split == 1) ? B_lo : B_hi;
        #pragma unroll
        for (int step = 0; step < 8; step++) {
            int kb = step * 8;               // b32 offset for this k16 chunk
            uint32_t a[2][4], b[4][2];
            #pragma unroll
            for (int mt = 0; mt < 2; mt++) {
                int r = wm + mt * 16 + g;
                a[mt][0] = Ap[r * PITCH + kb + tig];
                a[mt][1] = Ap[(r + 8) * PITCH + kb + tig];
                a[mt][2] = Ap[r * PITCH + kb + tig + 4];
                a[mt][3] = Ap[(r + 8) * PITCH + kb + tig + 4];
            }
            #pragma unroll
            for (int nt = 0; nt < 4; nt++) {
                int c = wn + nt * 8 + g;
                b[nt][0] = Bp[c * PITCH + kb + tig];
                b[nt][1] = Bp[c * PITCH + kb + tig + 4];
            }
            #pragma unroll
            for (int mt = 0; mt < 2; mt++)
                #pragma unroll
                for (int nt = 0; nt < 4; nt++)
                    mma16816(acc[mt][nt], a[mt], b[nt]);
        }
    }

    // --- epilogue: scale by dinv[row]; fp32 stores + fp16 copy ---
    #pragma unroll
    for (int mt = 0; mt < 2; mt++) {
        #pragma unroll
        for (int half = 0; half < 2; half++) {
            int row = m0 + wm + mt * 16 + g + half * 8;
            if (row >= nrows) continue;
            float dv = g_dinv[row];
            #pragma unroll
            for (int nt = 0; nt < 4; nt++) {
                float2 v;
                v.x = dv * acc[mt][nt][half * 2 + 0];
                v.y = dv * acc[mt][nt][half * 2 + 1];
                size_t off = (size_t)row * D + wn + nt * 8 + tig * 2;
                *(float2*)&g_buf[off] = v;
                *(__half2*)&g_h16[off] = __floats2half2_rn(v.x, v.y);
            }
        }
    }
}

// ---------------- aggregate: out[v] = relu(dinv[v]*(g[v] + sum g16[nbr]) + b) ----------------
// Warp per dst node. Self term fp32; neighbor gathers fp16 (256B/edge), fp32 accum.
template <bool TO_GX>
__global__ __launch_bounds__(256)
void aggregate(const float* __restrict__ bias, float* __restrict__ outp, int n) {
    int w    = (blockIdx.x * blockDim.x + threadIdx.x) >> 5;
    int lane = threadIdx.x & 31;
    if (w >= n) return;

    int beg = g_rowptr[w];
    int end = g_rowptr[w + 1];
    size_t col = (size_t)lane * 4;

    float4 acc = *(const float4*)&g_buf[(size_t)w * D + col];   // self-loop, fp32

    int e = beg;
    for (; e + 2 <= end; e += 2) {
        int s0 = __ldg(&g_csr[e]);
        int s1 = __ldg(&g_csr[e + 1]);
        uint2 u0 = *(const uint2*)&g_h16[(size_t)s0 * D + col];
        uint2 u1 = *(const uint2*)&g_h16[(size_t)s1 * D + col];
        float2 a0 = __half22float2(*(__half2*)&u0.x);
        float2 a1 = __half22float2(*(__half2*)&u0.y);
        float2 b0 = __half22float2(*(__half2*)&u1.x);
        float2 b1 = __half22float2(*(__half2*)&u1.y);
        acc.x += a0.x + b0.x;
        acc.y += a0.y + b0.y;
        acc.z += a1.x + b1.x;
        acc.w += a1.y + b1.y;
    }
    if (e < end) {
        int s0 = __ldg(&g_csr[e]);
        uint2 u0 = *(const uint2*)&g_h16[(size_t)s0 * D + col];
        float2 a0 = __half22float2(*(__half2*)&u0.x);
        float2 a1 = __half22float2(*(__half2*)&u0.y);
        acc.x += a0.x; acc.y += a0.y; acc.z += a1.x; acc.w += a1.y;
    }

    float dv = g_dinv[w];
    float4 b = *(const float4*)&bias[col];
    float4 r;
    r.x = fmaxf(fmaf(dv, acc.x, b.x), 0.f);
    r.y = fmaxf(fmaf(dv, acc.y, b.y), 0.f);
    r.z = fmaxf(fmaf(dv, acc.z, b.z), 0.f);
    r.w = fmaxf(fmaf(dv, acc.w, b.w), 0.f);

    float* out = TO_GX ? g_x : outp;
    *(float4*)&out[(size_t)w * D + col] = r;
}

// ---------------- launch ----------------
extern "C" void kernel_launch(void* const* d_in, const int* in_sizes, int n_in,
                              void* d_out, int out_size) {
    const float* node_fts = (const float*)d_in[0];
    const int*   edge     = (const int*)d_in[1];   // int32
    const float* W[3] = { (const float*)d_in[2], (const float*)d_in[4], (const float*)d_in[6] };
    const float* B[3] = { (const float*)d_in[3], (const float*)d_in[5], (const float*)d_in[7] };

    const int nrows = in_sizes[0] / D;
    const int E     = in_sizes[1] / 2;
    const int* src  = edge;
    const int* dst  = edge + E;

    static bool attr_done = false;
    if (!attr_done) {
        cudaFuncSetAttribute(gemm_mma<false>, cudaFuncAttributeMaxDynamicSharedMemorySize, SM_TOTAL);
        cudaFuncSetAttribute(gemm_mma<true>,  cudaFuncAttributeMaxDynamicSharedMemorySize, SM_TOTAL);
        attr_done = true;
    }

    const int scan_blocks = (nrows + SCAN_B - 1) / SCAN_B;

    // ---- CSR build + dinv + W^T splits (once per call) ----
    cnt_zero<<<(nrows + 255) / 256, 256>>>(nrows);
    cnt_count<<<(E + 255) / 256, 256>>>(dst, E);
    scanA<<<scan_blocks, SCAN_B>>>(nrows);
    scanB<<<1, MAX_BLOCKS>>>(scan_blocks, nrows);
    scanC<<<scan_blocks, SCAN_B>>>(nrows);
    fill_csr<<<(E + 255) / 256, 256>>>(src, dst, E);
    prep_wt<<<(3 * D * D + 255) / 256, 256>>>(W[0], W[1], W[2]);

    const int gemm_blocks = (nrows + 127) / 128;
    const int agg_blocks  = (nrows * 32 + 255) / 256;

    // Layer 1
    gemm_mma<false><<<gemm_blocks, 512, SM_TOTAL>>>(node_fts, 0, nrows);
    aggregate<true><<<agg_blocks, 256>>>(B[0], nullptr, nrows);
    // Layer 2
    gemm_mma<true><<<gemm_blocks, 512, SM_TOTAL>>>(nullptr, 1, nrows);
    aggregate<true><<<agg_blocks, 256>>>(B[1], nullptr, nrows);
    // Layer 3
    gemm_mma<true><<<gemm_blocks, 512, SM_TOTAL>>>(nullptr, 2, nrows);
    aggregate<false><<<agg_blocks, 256>>>(B[2], (float*)d_out, nrows);
}

// round 9
// speedup vs baseline: 1.0059x; 1.0059x over previous
#include <cuda_runtime.h>
#include <cuda_bf16.h>
#include <cstdint>

#define N_MAX 100000
#define E_MAX 1700000
#define D 128
#define SCAN_B 1024
#define MAX_BLOCKS 128   // >= ceil(N_MAX/SCAN_B) = 98, power of two for scanB

// ---------------- scratch (static device globals) ----------------
__device__ __align__(16) float g_buf[N_MAX * D];            // g[u] = dinv[u]*(X@W)[u]
__device__ __align__(16) __nv_bfloat16 g_xh[N_MAX * D];     // activation hi split (GEMM input)
__device__ __align__(16) __nv_bfloat16 g_xl[N_MAX * D];     // activation lo split
__device__ float g_dinv[N_MAX];
__device__ int   g_cnt[N_MAX];
__device__ int   g_rowptr[N_MAX + 1];
__device__ int   g_cursor[N_MAX];
__device__ int   g_blocksum[MAX_BLOCKS];
__device__ int   g_blockoff[MAX_BLOCKS];
__device__ int   g_csr[E_MAX];
__device__ __align__(16) __nv_bfloat16 g_wt_hi[3 * D * D];  // W^T hi split, [l][n][k]
__device__ __align__(16) __nv_bfloat16 g_wt_lo[3 * D * D];  // W^T lo split

// ---------------- small helpers ----------------
__device__ __forceinline__ uint32_t smem_u32(const void* p) {
    uint32_t a;
    asm("{ .reg .u64 t; cvta.to.shared.u64 t, %1; cvt.u32.u64 %0, t; }" : "=r"(a) : "l"(p));
    return a;
}
__device__ __forceinline__ void cp_async16(uint32_t saddr, const void* gptr, bool valid) {
    int sz = valid ? 16 : 0;
    asm volatile("cp.async.cg.shared.global [%0], [%1], 16, %2;"
                 :: "r"(saddr), "l"(gptr), "r"(sz));
}
#define CP_COMMIT()   asm volatile("cp.async.commit_group;")
#define CP_WAIT_ALL() asm volatile("cp.async.wait_all;" ::: "memory")

// ---------------- degree histogram / scan / CSR ----------------
__global__ void cnt_zero(int n) {
    int i = blockIdx.x * blockDim.x + threadIdx.x;
    if (i < n) g_cnt[i] = 0;
}
__global__ void cnt_count(const int* __restrict__ dst, int E) {
    int i = blockIdx.x * blockDim.x + threadIdx.x;
    if (i < E) atomicAdd(&g_cnt[__ldg(&dst[i])], 1);
}
__global__ void scanA(int n) {
    __shared__ int s[SCAN_B];
    int i = blockIdx.x * SCAN_B + threadIdx.x;
    s[threadIdx.x] = (i < n) ? g_cnt[i] : 0;
    __syncthreads();
    for (int off = SCAN_B / 2; off > 0; off >>= 1) {
        if (threadIdx.x < off) s[threadIdx.x] += s[threadIdx.x + off];
        __syncthreads();
    }
    if (threadIdx.x == 0) g_blocksum[blockIdx.x] = s[0];
}
__global__ void scanB(int nblocks, int n) {
    __shared__ int s[MAX_BLOCKS];
    int t = threadIdx.x;
    int v = (t < nblocks) ? g_blocksum[t] : 0;
    s[t] = v; __syncthreads();
    for (int off = 1; off < MAX_BLOCKS; off <<= 1) {
        int u = (t >= off) ? s[t - off] : 0;
        __syncthreads();
        s[t] += u;
        __syncthreads();
    }
    if (t < nblocks) g_blockoff[t] = s[t] - v;
    if (t == nblocks - 1) g_rowptr[n] = s[t];
}
__global__ void scanC(int n) {
    __shared__ int s[SCAN_B];
    int i = blockIdx.x * SCAN_B + threadIdx.x;
    int v = (i < n) ? g_cnt[i] : 0;
    s[threadIdx.x] = v;
    __syncthreads();
    for (int off = 1; off < SCAN_B; off <<= 1) {
        int t = (threadIdx.x >= off) ? s[threadIdx.x - off] : 0;
        __syncthreads();
        s[threadIdx.x] += t;
        __syncthreads();
    }
    if (i < n) {
        int excl = s[threadIdx.x] - v + g_blockoff[blockIdx.x];
        g_rowptr[i] = excl;
        g_cursor[i] = excl;
        g_dinv[i]   = rsqrtf((float)(v + 1));
    }
}
__global__ void fill_csr(const int* __restrict__ src, const int* __restrict__ dst, int E) {
    int i = blockIdx.x * blockDim.x + threadIdx.x;
    if (i < E) {
        int d = __ldg(&dst[i]);
        int pos = atomicAdd(&g_cursor[d], 1);
        g_csr[pos] = __ldg(&src[i]);
    }
}

// ---------------- once-per-call prep ----------------
__global__ void prep_wt(const float* __restrict__ W0, const float* __restrict__ W1,
                        const float* __restrict__ W2) {
    int idx = blockIdx.x * blockDim.x + threadIdx.x;
    if (idx >= 3 * D * D) return;
    int l = idx / (D * D);
    int r = idx % (D * D);
    int n = r >> 7, k = r & 127;
    const float* W = (l == 0) ? W0 : ((l == 1) ? W1 : W2);
    float f = W[k * D + n];
    __nv_bfloat16 h = __float2bfloat16(f);
    g_wt_hi[idx] = h;
    g_wt_lo[idx] = __float2bfloat16(f - __bfloat162float(h));
}

// convert node_fts fp32 -> bf16 hi/lo splits (layer-1 GEMM input)
__global__ void prep_x(const float* __restrict__ X, int total4) {
    int i = blockIdx.x * blockDim.x + threadIdx.x;   // over float4 slots
    if (i >= total4) return;
    float4 v = *(const float4*)&X[i * 4];
    __nv_bfloat162 h01, h23, l01, l23;
    h01.x = __float2bfloat16(v.x); h01.y = __float2bfloat16(v.y);
    h23.x = __float2bfloat16(v.z); h23.y = __float2bfloat16(v.w);
    l01.x = __float2bfloat16(v.x - __bfloat162float(h01.x));
    l01.y = __float2bfloat16(v.y - __bfloat162float(h01.y));
    l23.x = __float2bfloat16(v.z - __bfloat162float(h23.x));
    l23.y = __float2bfloat16(v.w - __bfloat162float(h23.y));
    uint2 uh = make_uint2(*(uint32_t*)&h01, *(uint32_t*)&h23);
    uint2 ul = make_uint2(*(uint32_t*)&l01, *(uint32_t*)&l23);
    *(uint2*)&g_xh[i * 4] = uh;
    *(uint2*)&g_xl[i * 4] = ul;
}

// ---------------- bf16x3 GEMM (mma.sync), bf16 inputs, M=64 tile ----------------
// g_buf = dinv .* (X @ W). 256 threads = 8 warps (2m x 4n), warp tile 32x32.
#define PITCH 68   // b32 per smem row (dense row = 64 b32) -> conflict-free frags
#define A_ROWS 64
#define SM_A (A_ROWS * PITCH)     // per split, b32
#define SM_B (128 * PITCH)        // per split, b32
#define SM_TOTAL_B ((2 * SM_A + 2 * SM_B) * 4)   // 104448 bytes -> 2 CTAs/SM

__device__ __forceinline__ void mma16816(float* c, const uint32_t* a, const uint32_t* b) {
    asm volatile(
        "mma.sync.aligned.m16n8k16.row.col.f32.bf16.bf16.f32 "
        "{%0,%1,%2,%3}, {%4,%5,%6,%7}, {%8,%9}, {%0,%1,%2,%3};"
        : "+f"(c[0]), "+f"(c[1]), "+f"(c[2]), "+f"(c[3])
        : "r"(a[0]), "r"(a[1]), "r"(a[2]), "r"(a[3]), "r"(b[0]), "r"(b[1]));
}

__global__ __launch_bounds__(256, 2)
void gemm_mma(int layer, int nrows) {
    extern __shared__ uint32_t smem[];
    uint32_t* A_hi = smem;
    uint32_t* A_lo = A_hi + SM_A;
    uint32_t* B_hi = A_lo + SM_A;
    uint32_t* B_lo = B_hi + SM_B;

    const int tid = threadIdx.x;
    const int m0  = blockIdx.x * A_ROWS;
    const uint32_t sb = smem_u32(smem);

    // --- async loads: A tile (64 rows x 256B per split), B tile (128 rows x 256B per split)
    // A: 64*16 = 1024 chunks per split -> 4 per thread
    #pragma unroll
    for (int i = 0; i < 4; i++) {
        int id  = tid + i * 256;            // 0..1023
        int row = id >> 4;                  // 64 rows
        int q   = id & 15;                  // 16B chunk (8 bf16)
        int gr  = m0 + row;
        bool ok = gr < nrows;
        size_t gof = (size_t)gr * D + q * 8;
        uint32_t so = (row * PITCH + q * 4) * 4;
        cp_async16(sb + (uint32_t)((char*)A_hi - (char*)smem) + so, &g_xh[gof], ok);
        cp_async16(sb + (uint32_t)((char*)A_lo - (char*)smem) + so, &g_xl[gof], ok);
    }
    // B: 128*16 = 2048 chunks per split -> 8 per thread
    {
        const __nv_bfloat16* wh = &g_wt_hi[layer * D * D];
        const __nv_bfloat16* wl = &g_wt_lo[layer * D * D];
        #pragma unroll
        for (int i = 0; i < 8; i++) {
            int id = tid + i * 256;         // 0..2047
            int n  = id >> 4;               // 128 rows
            int q  = id & 15;
            size_t gof = (size_t)n * D + q * 8;
            uint32_t so = (n * PITCH + q * 4) * 4;
            cp_async16(sb + (uint32_t)((char*)B_hi - (char*)smem) + so, &wh[gof], true);
            cp_async16(sb + (uint32_t)((char*)B_lo - (char*)smem) + so, &wl[gof], true);
        }
    }
    CP_COMMIT();
    CP_WAIT_ALL();
    __syncthreads();

    // --- warp MMA ---
    const int wid  = tid >> 5;
    const int lane = tid & 31;
    const int g    = lane >> 2;             // 0..7
    const int tig  = lane & 3;              // 0..3
    const int wm   = (wid & 1) * 32;        // M in {0,32}
    const int wn   = (wid >> 1) * 32;       // N in {0,32,64,96}

    float acc[2][4][4];
    #pragma unroll
    for (int mt = 0; mt < 2; mt++)
        #pragma unroll
        for (int nt = 0; nt < 4; nt++)
            #pragma unroll
            for (int e = 0; e < 4; e++) acc[mt][nt][e] = 0.f;

    #pragma unroll
    for (int split = 0; split < 3; split++) {
        const uint32_t* Ap = (split == 2) ? A_lo : A_hi;
        const uint32_t* Bp = (split == 1) ? B_lo : B_hi;
        #pragma unroll
        for (int step = 0; step < 8; step++) {
            int kb = step * 8;
            uint32_t a[2][4], b[4][2];
            #pragma unroll
            for (int mt = 0; mt < 2; mt++) {
                int r = wm + mt * 16 + g;
                a[mt][0] = Ap[r * PITCH + kb + tig];
                a[mt][1] = Ap[(r + 8) * PITCH + kb + tig];
                a[mt][2] = Ap[r * PITCH + kb + tig + 4];
                a[mt][3] = Ap[(r + 8) * PITCH + kb + tig + 4];
            }
            #pragma unroll
            for (int nt = 0; nt < 4; nt++) {
                int c = wn + nt * 8 + g;
                b[nt][0] = Bp[c * PITCH + kb + tig];
                b[nt][1] = Bp[c * PITCH + kb + tig + 4];
            }
            #pragma unroll
            for (int mt = 0; mt < 2; mt++)
                #pragma unroll
                for (int nt = 0; nt < 4; nt++)
                    mma16816(acc[mt][nt], a[mt], b[nt]);
        }
    }

    // --- epilogue: scale by dinv[row], fp32 stores to g_buf ---
    #pragma unroll
    for (int mt = 0; mt < 2; mt++) {
        #pragma unroll
        for (int half = 0; half < 2; half++) {
            int row = m0 + wm + mt * 16 + g + half * 8;
            if (row >= nrows) continue;
            float dv = g_dinv[row];
            #pragma unroll
            for (int nt = 0; nt < 4; nt++) {
                float2 v;
                v.x = dv * acc[mt][nt][half * 2 + 0];
                v.y = dv * acc[mt][nt][half * 2 + 1];
                *(float2*)&g_buf[(size_t)row * D + wn + nt * 8 + tig * 2] = v;
            }
        }
    }
}

// ---------------- aggregate ----------------
// out[v] = relu(dinv[v]*(g[v] + sum g[nbr]) + b). Warp per node, fp32 gathers.
// TO_GX=true: emit bf16 hi/lo splits (next GEMM input). Else fp32 to d_out.
template <bool TO_GX>
__global__ __launch_bounds__(256)
void aggregate(const float* __restrict__ bias, float* __restrict__ outp, int n) {
    int w    = (blockIdx.x * blockDim.x + threadIdx.x) >> 5;
    int lane = threadIdx.x & 31;
    if (w >= n) return;

    int beg = g_rowptr[w];
    int end = g_rowptr[w + 1];
    size_t col = (size_t)lane * 4;

    float4 acc = *(const float4*)&g_buf[(size_t)w * D + col];   // self-loop

    int e = beg;
    for (; e + 2 <= end; e += 2) {
        int s0 = __ldg(&g_csr[e]);
        int s1 = __ldg(&g_csr[e + 1]);
        float4 v0 = *(const float4*)&g_buf[(size_t)s0 * D + col];
        float4 v1 = *(const float4*)&g_buf[(size_t)s1 * D + col];
        acc.x += v0.x + v1.x;
        acc.y += v0.y + v1.y;
        acc.z += v0.z + v1.z;
        acc.w += v0.w + v1.w;
    }
    if (e < end) {
        int s0 = __ldg(&g_csr[e]);
        float4 v0 = *(const float4*)&g_buf[(size_t)s0 * D + col];
        acc.x += v0.x; acc.y += v0.y; acc.z += v0.z; acc.w += v0.w;
    }

    float dv = g_dinv[w];
    float4 b = *(const float4*)&bias[col];
    float4 r;
    r.x = fmaxf(fmaf(dv, acc.x, b.x), 0.f);
    r.y = fmaxf(fmaf(dv, acc.y, b.y), 0.f);
    r.z = fmaxf(fmaf(dv, acc.z, b.z), 0.f);
    r.w = fmaxf(fmaf(dv, acc.w, b.w), 0.f);

    if (TO_GX) {
        __nv_bfloat162 h01, h23, l01, l23;
        h01.x = __float2bfloat16(r.x); h01.y = __float2bfloat16(r.y);
        h23.x = __float2bfloat16(r.z); h23.y = __float2bfloat16(r.w);
        l01.x = __float2bfloat16(r.x - __bfloat162float(h01.x));
        l01.y = __float2bfloat16(r.y - __bfloat162float(h01.y));
        l23.x = __float2bfloat16(r.z - __bfloat162float(h23.x));
        l23.y = __float2bfloat16(r.w - __bfloat162float(h23.y));
        size_t off = (size_t)w * D + col;
        *(uint2*)&g_xh[off] = make_uint2(*(uint32_t*)&h01, *(uint32_t*)&h23);
        *(uint2*)&g_xl[off] = make_uint2(*(uint32_t*)&l01, *(uint32_t*)&l23);
    } else {
        *(float4*)&outp[(size_t)w * D + col] = r;
    }
}

// ---------------- launch ----------------
extern "C" void kernel_launch(void* const* d_in, const int* in_sizes, int n_in,
                              void* d_out, int out_size) {
    const float* node_fts = (const float*)d_in[0];
    const int*   edge     = (const int*)d_in[1];   // int32
    const float* W[3] = { (const float*)d_in[2], (const float*)d_in[4], (const float*)d_in[6] };
    const float* B[3] = { (const float*)d_in[3], (const float*)d_in[5], (const float*)d_in[7] };

    const int nrows = in_sizes[0] / D;
    const int E     = in_sizes[1] / 2;
    const int* src  = edge;
    const int* dst  = edge + E;

    static bool attr_done = false;
    if (!attr_done) {
        cudaFuncSetAttribute(gemm_mma, cudaFuncAttributeMaxDynamicSharedMemorySize, SM_TOTAL_B);
        attr_done = true;
    }

    const int scan_blocks = (nrows + SCAN_B - 1) / SCAN_B;

    // ---- CSR build + dinv + W^T/X splits (once per call) ----
    cnt_zero<<<(nrows + 255) / 256, 256>>>(nrows);
    cnt_count<<<(E + 255) / 256, 256>>>(dst, E);
    scanA<<<scan_blocks, SCAN_B>>>(nrows);
    scanB<<<1, MAX_BLOCKS>>>(scan_blocks, nrows);
    scanC<<<scan_blocks, SCAN_B>>>(nrows);
    fill_csr<<<(E + 255) / 256, 256>>>(src, dst, E);
    prep_wt<<<(3 * D * D + 255) / 256, 256>>>(W[0], W[1], W[2]);
    const int total4 = nrows * D / 4;
    prep_x<<<(total4 + 255) / 256, 256>>>(node_fts, total4);

    const int gemm_blocks = (nrows + A_ROWS - 1) / A_ROWS;
    const int agg_blocks  = (nrows * 32 + 255) / 256;

    // Layer 1
    gemm_mma<<<gemm_blocks, 256, SM_TOTAL_B>>>(0, nrows);
    aggregate<true><<<agg_blocks, 256>>>(B[0], nullptr, nrows);
    // Layer 2
    gemm_mma<<<gemm_blocks, 256, SM_TOTAL_B>>>(1, nrows);
    aggregate<true><<<agg_blocks, 256>>>(B[1], nullptr, nrows);
    // Layer 3
    gemm_mma<<<gemm_blocks, 256, SM_TOTAL_B>>>(2, nrows);
    aggregate<false><<<agg_blocks, 256>>>(B[2], (float*)d_out, nrows);
}